// round 2
// baseline (speedup 1.0000x reference)
#include <cuda_runtime.h>

#define SCALING 0.17677669529663687f

// ---------------------------------------------------------------------------
// Scratch (static device globals — allowed; no runtime allocation)
// ---------------------------------------------------------------------------
__device__ float g_proj[9][32][1024][32];   // 37.7 MB  head-major projections
__device__ float g_mask[32][1024 * 1024];   // 134 MB   local_mask per bh
__device__ float g_attn_pre[4096 * 256];    // 4 MB     attn before out-proj

// ---------------------------------------------------------------------------
// warp helpers
// ---------------------------------------------------------------------------
__device__ __forceinline__ float warp_iscan(float v, int lane) {
    #pragma unroll
    for (int o = 1; o < 32; o <<= 1) {
        float u = __shfl_up_sync(0xffffffffu, v, o);
        if (lane >= o) v += u;
    }
    return v;
}
__device__ __forceinline__ float warp_sscan(float v, int lane) {
    #pragma unroll
    for (int o = 1; o < 32; o <<= 1) {
        float u = __shfl_down_sync(0xffffffffu, v, o);
        if (lane + o < 32) v += u;
    }
    return v;
}
// softmax over a 1024-long row in SMEM, one warp
__device__ __forceinline__ void warp_softmax_row(float* row, int lane) {
    float m = -1e30f;
    #pragma unroll
    for (int q = 0; q < 32; q++) m = fmaxf(m, row[q * 32 + lane]);
    #pragma unroll
    for (int o = 16; o; o >>= 1) m = fmaxf(m, __shfl_xor_sync(0xffffffffu, m, o));
    float ssum = 0.f;
    #pragma unroll
    for (int q = 0; q < 32; q++) {
        float e = __expf(row[q * 32 + lane] - m);
        row[q * 32 + lane] = e;
        ssum += e;
    }
    #pragma unroll
    for (int o = 16; o; o >>= 1) ssum += __shfl_xor_sync(0xffffffffu, ssum, o);
    float inv = 1.0f / ssum;
    #pragma unroll
    for (int q = 0; q < 32; q++) row[q * 32 + lane] *= inv;
}

// ---------------------------------------------------------------------------
// Kernel 1: packed in-projection.  C[4096 x 2304] = X_sel @ W^T + b  (scaled)
// scattered into g_proj[j][bh][s][d]
// ---------------------------------------------------------------------------
__global__ void __launch_bounds__(256) proj_kernel(
        const float* __restrict__ xq, const float* __restrict__ xk,
        const float* __restrict__ xv, const float* __restrict__ W,
        const float* __restrict__ bias)
{
    __shared__ float As[16][68];
    __shared__ float Bs[16][68];
    int ct = blockIdx.x;                 // 36 column tiles of 64
    int rt = blockIdx.y;                 // 64 row tiles of 64
    int j = ct >> 2;                     // projection slice (4 tiles per slice)
    const float* X = (j == 2) ? xv
                   : ((j == 1 || j == 4 || j == 6 || j == 8) ? xk : xq);
    int t = threadIdx.x;
    int tx = t & 15, ty = t >> 4;
    int row0 = rt * 64, col0 = ct * 64;
    float acc[4][4] = {};
    for (int kt = 0; kt < 256; kt += 16) {
        #pragma unroll
        for (int l = 0; l < 4; l++) {
            int u = t + l * 256;
            int kk = u & 15, m = u >> 4;
            As[kk][m] = X[(row0 + m) * 256 + kt + kk];
            Bs[kk][m] = W[(col0 + m) * 256 + kt + kk];
        }
        __syncthreads();
        #pragma unroll
        for (int kk = 0; kk < 16; kk++) {
            float4 av = *(const float4*)(&As[kk][ty * 4]);
            float4 bv = *(const float4*)(&Bs[kk][tx * 4]);
            float a[4] = {av.x, av.y, av.z, av.w};
            float b[4] = {bv.x, bv.y, bv.z, bv.w};
            #pragma unroll
            for (int i = 0; i < 4; i++)
                #pragma unroll
                for (int c = 0; c < 4; c++)
                    acc[i][c] += a[i] * b[c];
        }
        __syncthreads();
    }
    float scale = (j == 0 || j == 7) ? SCALING : 1.0f;
    #pragma unroll
    for (int i = 0; i < 4; i++) {
        int row = row0 + ty * 4 + i;
        int s = row >> 2, b = row & 3;
        #pragma unroll
        for (int c = 0; c < 4; c++) {
            int col = col0 + tx * 4 + c;
            int eo = col - j * 256;
            float val = (acc[i][c] + bias[col]) * scale;
            g_proj[j][b * 8 + (eo >> 5)][s][eo & 31] = val;
        }
    }
}

// ---------------------------------------------------------------------------
// shared GEMM helper: logits[16][1024] tile, Q in Qt[d*16+i], K staged in KT
// ---------------------------------------------------------------------------
#define STAGE_K_TILE(Ksrc, ct)                                               \
    for (int u = threadIdx.x * 4; u < 8192; u += 1024) {                     \
        int col = u >> 5, dd = u & 31;                                       \
        float4 kv = *(const float4*)((Ksrc) + ((ct) * 256 + col) * 32 + dd); \
        KT[col * 33 + dd + 0] = kv.x;                                        \
        KT[col * 33 + dd + 1] = kv.y;                                        \
        KT[col * 33 + dd + 2] = kv.z;                                        \
        KT[col * 33 + dd + 3] = kv.w;                                        \
    }

#define LOGIT_MAC(acc)                                                       \
    _Pragma("unroll")                                                        \
    for (int d = 0; d < 32; d++) {                                           \
        float kv = KT[t * 33 + d];                                           \
        const float4* qp = (const float4*)(Qt + d * 16);                     \
        float4 q0 = qp[0], q1 = qp[1], q2 = qp[2], q3 = qp[3];               \
        acc[0]  += q0.x * kv; acc[1]  += q0.y * kv;                          \
        acc[2]  += q0.z * kv; acc[3]  += q0.w * kv;                          \
        acc[4]  += q1.x * kv; acc[5]  += q1.y * kv;                          \
        acc[6]  += q1.z * kv; acc[7]  += q1.w * kv;                          \
        acc[8]  += q2.x * kv; acc[9]  += q2.y * kv;                          \
        acc[10] += q2.z * kv; acc[11] += q2.w * kv;                          \
        acc[12] += q3.x * kv; acc[13] += q3.y * kv;                          \
        acc[14] += q3.z * kv; acc[15] += q3.w * kv;                          \
    }

// ---------------------------------------------------------------------------
// Kernel F1: per (bh, 16 rows): left/right logits -> softmax ->
// prefix/suffix transforms -> local_mask rows to gmem
// dyn smem: Ls[16*1024] Rs[16*1024] KT[256*33] Qt[512] = 166912 B
// ---------------------------------------------------------------------------
__global__ void __launch_bounds__(256) f1_kernel()
{
    extern __shared__ float sm[];
    float* Ls = sm;                 // 16384
    float* Rs = sm + 16384;         // 16384
    float* KT = sm + 32768;         // 8448
    float* Qt = sm + 41216;         // 512
    int t = threadIdx.x, lane = t & 31, w = t >> 5;
    int rt = blockIdx.x, bh = blockIdx.y;
    int row0 = rt * 16;

    for (int m = 0; m < 2; m++) {
        const float* Qsrc = &g_proj[m == 0 ? 3 : 5][bh][0][0];
        const float* Ksrc = &g_proj[m == 0 ? 4 : 6][bh][0][0];
        float* Obuf = (m == 0) ? Ls : Rs;
        __syncthreads();
        for (int u = t; u < 512; u += 256) {
            int i = u >> 5, d = u & 31;
            Qt[d * 16 + i] = Qsrc[(row0 + i) * 32 + d];
        }
        for (int ct = 0; ct < 4; ct++) {
            __syncthreads();
            STAGE_K_TILE(Ksrc, ct)
            __syncthreads();
            float acc[16];
            #pragma unroll
            for (int i = 0; i < 16; i++) acc[i] = 0.f;
            LOGIT_MAC(acc)
            #pragma unroll
            for (int i = 0; i < 16; i++) Obuf[i * 1024 + ct * 256 + t] = acc[i];
        }
    }
    __syncthreads();
    // softmax (warp w owns rows w and w+8 of both matrices)
    warp_softmax_row(Ls + w * 1024, lane);
    warp_softmax_row(Ls + (w + 8) * 1024, lane);
    warp_softmax_row(Rs + w * 1024, lane);
    warp_softmax_row(Rs + (w + 8) * 1024, lane);

    // prefix/suffix transforms + mask write (warp-local rows, no block sync)
    for (int rr = 0; rr < 2; rr++) {
        int r = w + rr * 8;
        float* Lrow = Ls + r * 1024;
        float* Rrow = Rs + r * 1024;
        float sfL[32], sfR[32];
        {
            float ps[32];
            #pragma unroll
            for (int q = 0; q < 32; q++) {
                float v = Lrow[q * 32 + lane];
                ps[q] = warp_iscan(v, lane);
                sfL[q] = warp_sscan(v, lane);
            }
            float run = 0.f;
            #pragma unroll
            for (int q = 0; q < 32; q++) { run += ps[q]; Lrow[q * 32 + lane] = run; }
            run = 0.f;
            #pragma unroll
            for (int q = 31; q >= 0; q--) { run += sfL[q]; sfL[q] = run; }
        }
        {
            float ps[32];
            #pragma unroll
            for (int q = 0; q < 32; q++) {
                float v = Rrow[q * 32 + lane];
                ps[q] = warp_iscan(v, lane);
                sfR[q] = warp_sscan(v, lane);
            }
            float run = 0.f;
            #pragma unroll
            for (int q = 0; q < 32; q++) { run += ps[q]; Rrow[q * 32 + lane] = run; }
            run = 0.f;
            #pragma unroll
            for (int q = 31; q >= 0; q--) { run += sfR[q]; sfR[q] = run; }
        }
        float* mout = &g_mask[bh][(size_t)(row0 + r) * 1024];
        #pragma unroll
        for (int q = 0; q < 32; q++) {
            // fw = P(L)*Sf(R), bw = Sf(L)*P(R)
            mout[q * 32 + lane] = Lrow[q * 32 + lane] * sfR[q]
                                + sfL[q] * Rrow[q * 32 + lane];
        }
    }
}

// ---------------------------------------------------------------------------
// Kernel F2: global/local logits, combine with mask, softmax, AV
// dyn smem: Cs[16*1024] KT[256*33] Qt[512] = 101376 B
// ---------------------------------------------------------------------------
__global__ void __launch_bounds__(256) f2_kernel()
{
    extern __shared__ float sm[];
    float* Cs = sm;                 // 16384
    float* KT = sm + 16384;         // 8448
    float* Qt = sm + 24832;         // 512
    int t = threadIdx.x, lane = t & 31, w = t >> 5;
    int rt = blockIdx.x, bh = blockIdx.y;
    int row0 = rt * 16;

    for (int m = 0; m < 2; m++) {
        const float* Qsrc = &g_proj[m == 0 ? 0 : 7][bh][0][0];
        const float* Ksrc = &g_proj[m == 0 ? 1 : 8][bh][0][0];
        __syncthreads();
        for (int u = t; u < 512; u += 256) {
            int i = u >> 5, d = u & 31;
            Qt[d * 16 + i] = Qsrc[(row0 + i) * 32 + d];
        }
        for (int ct = 0; ct < 4; ct++) {
            __syncthreads();
            STAGE_K_TILE(Ksrc, ct)
            __syncthreads();
            float acc[16];
            #pragma unroll
            for (int i = 0; i < 16; i++) acc[i] = 0.f;
            LOGIT_MAC(acc)
            if (m == 0) {
                #pragma unroll
                for (int i = 0; i < 16; i++) Cs[i * 1024 + ct * 256 + t] = acc[i];
            } else {
                #pragma unroll
                for (int i = 0; i < 16; i++) {
                    float mval = g_mask[bh][(size_t)(row0 + i) * 1024 + ct * 256 + t];
                    int idx = i * 1024 + ct * 256 + t;
                    Cs[idx] = 0.1f * Cs[idx] + acc[i] * mval;
                }
            }
        }
    }
    __syncthreads();
    warp_softmax_row(Cs + w * 1024, lane);
    warp_softmax_row(Cs + (w + 8) * 1024, lane);
    __syncthreads();

    // AV: out[16][32] = Cs @ V
    int d = t & 31, ip = t >> 5;
    int i0 = ip, i1 = ip + 8;
    float a0 = 0.f, a1 = 0.f;
    const float* Vsrc = &g_proj[2][bh][0][0];
    for (int jt = 0; jt < 4; jt++) {
        __syncthreads();
        STAGE_K_TILE(Vsrc, jt)          // reuse KT as V tile
        __syncthreads();
        #pragma unroll
        for (int j = 0; j < 256; j += 4) {
            float4 c0 = *(const float4*)(Cs + i0 * 1024 + jt * 256 + j);
            float4 c1 = *(const float4*)(Cs + i1 * 1024 + jt * 256 + j);
            float v0 = KT[(j + 0) * 33 + d], v1 = KT[(j + 1) * 33 + d];
            float v2 = KT[(j + 2) * 33 + d], v3 = KT[(j + 3) * 33 + d];
            a0 += c0.x * v0 + c0.y * v1 + c0.z * v2 + c0.w * v3;
            a1 += c1.x * v0 + c1.y * v1 + c1.z * v2 + c1.w * v3;
        }
    }
    int b = bh >> 3, h = bh & 7;
    g_attn_pre[((row0 + i0) * 4 + b) * 256 + h * 32 + d] = a0;
    g_attn_pre[((row0 + i1) * 4 + b) * 256 + h * 32 + d] = a1;
}

// ---------------------------------------------------------------------------
// Kernel 4: out-projection.  out[4096 x 256] = attn_pre @ out_w^T + out_b
// ---------------------------------------------------------------------------
__global__ void __launch_bounds__(256) outproj_kernel(
        const float* __restrict__ W, const float* __restrict__ bias,
        float* __restrict__ out)
{
    __shared__ float As[16][68];
    __shared__ float Bs[16][68];
    int ct = blockIdx.x;  // 4
    int rt = blockIdx.y;  // 64
    int t = threadIdx.x;
    int tx = t & 15, ty = t >> 4;
    int row0 = rt * 64, col0 = ct * 64;
    float acc[4][4] = {};
    for (int kt = 0; kt < 256; kt += 16) {
        #pragma unroll
        for (int l = 0; l < 4; l++) {
            int u = t + l * 256;
            int kk = u & 15, m = u >> 4;
            As[kk][m] = g_attn_pre[(row0 + m) * 256 + kt + kk];
            Bs[kk][m] = W[(col0 + m) * 256 + kt + kk];
        }
        __syncthreads();
        #pragma unroll
        for (int kk = 0; kk < 16; kk++) {
            float4 av = *(const float4*)(&As[kk][ty * 4]);
            float4 bv = *(const float4*)(&Bs[kk][tx * 4]);
            float a[4] = {av.x, av.y, av.z, av.w};
            float b[4] = {bv.x, bv.y, bv.z, bv.w};
            #pragma unroll
            for (int i = 0; i < 4; i++)
                #pragma unroll
                for (int c = 0; c < 4; c++)
                    acc[i][c] += a[i] * b[c];
        }
        __syncthreads();
    }
    #pragma unroll
    for (int i = 0; i < 4; i++) {
        int row = row0 + ty * 4 + i;
        #pragma unroll
        for (int c = 0; c < 4; c++) {
            int col = col0 + tx * 4 + c;
            out[row * 256 + col] = acc[i][c] + bias[col];
        }
    }
}

// ---------------------------------------------------------------------------
// Kernel 5: consistent_mask = sum over bh of g_mask
// ---------------------------------------------------------------------------
__global__ void __launch_bounds__(256) mask_reduce_kernel(float* __restrict__ out)
{
    int idx = blockIdx.x * 256 + threadIdx.x;
    float s = 0.f;
    #pragma unroll
    for (int bh = 0; bh < 32; bh++) s += g_mask[bh][idx];
    out[idx] = s;
}

// ---------------------------------------------------------------------------
extern "C" void kernel_launch(void* const* d_in, const int* in_sizes, int n_in,
                              void* d_out, int out_size)
{
    const float* q   = (const float*)d_in[0];
    const float* k   = (const float*)d_in[1];
    const float* v   = (const float*)d_in[2];
    const float* ipw = (const float*)d_in[3];
    const float* ipb = (const float*)d_in[4];
    const float* ow  = (const float*)d_in[5];
    const float* ob  = (const float*)d_in[6];
    float* out = (float*)d_out;

    cudaFuncSetAttribute(f1_kernel, cudaFuncAttributeMaxDynamicSharedMemorySize, 166912);
    cudaFuncSetAttribute(f2_kernel, cudaFuncAttributeMaxDynamicSharedMemorySize, 101376);

    proj_kernel<<<dim3(36, 64), 256>>>(q, k, v, ipw, ipb);
    f1_kernel<<<dim3(64, 32), 256, 166912>>>();
    f2_kernel<<<dim3(64, 32), 256, 101376>>>();
    outproj_kernel<<<dim3(4, 64), 256>>>(ow, ob, out);
    mask_reduce_kernel<<<4096, 256>>>(out + 1048576);
}